// round 1
// baseline (speedup 1.0000x reference)
#include <cuda_runtime.h>
#include <math.h>

// Problem shape (fixed)
static constexpr int Bb = 4;
static constexpr int Tt = 2048;
static constexpr int Dd = 1024;
static constexpr int Hh = 16;
static constexpr int HDd = 64;
static constexpr int DFf = 4096;
static constexpr int Mrows = Bb * Tt;   // 8192

// ---------------- scratch (device globals; no allocation allowed) ----------
__device__ float g_Q[(size_t)Mrows * Dd];
__device__ float g_K[(size_t)Mrows * Dd];
__device__ float g_V[(size_t)Mrows * Dd];
__device__ float g_attn[(size_t)Mrows * Dd];
__device__ float g_proj[(size_t)Mrows * Dd];
__device__ float g_h[(size_t)Mrows * Dd];
__device__ float g_ff1[(size_t)Mrows * DFf];
__device__ float g_ff2[(size_t)Mrows * Dd];

// ---------------- helpers ----------------
__device__ __forceinline__ float gelu_exact(float x) {
    return 0.5f * x * (1.0f + erff(x * 0.70710678118654752f));
}

// ---------------- GEMM: C[M,N] = A[M,K] @ B[K,N] (+bias)(+gelu) ------------
// 128x128 block, BK=8, 256 threads, 8x8 microtile per thread.
// EPI: 0 = none, 1 = +bias, 2 = +bias then exact gelu
template <int EPI>
__global__ __launch_bounds__(256) void gemm_kernel(
    const float* __restrict__ A, const float* __restrict__ Bm,
    const float* __restrict__ bias, float* __restrict__ C,
    int M, int N, int K)
{
    __shared__ float As[8][128];
    __shared__ float Bs[8][128];

    const int tid = threadIdx.x;
    const int tx = tid & 15;     // 0..15
    const int ty = tid >> 4;     // 0..15
    const int bm = blockIdx.y * 128;
    const int bn = blockIdx.x * 128;

    float acc[8][8];
#pragma unroll
    for (int i = 0; i < 8; i++)
#pragma unroll
        for (int j = 0; j < 8; j++) acc[i][j] = 0.0f;

    // A tile load: 128 rows x 8 cols = 1024 floats; one float4 per thread
    const int a_row = tid >> 1;          // 0..127
    const int a_c4  = (tid & 1) * 4;     // 0 or 4
    // B tile load: 8 rows x 128 cols; one float4 per thread
    const int b_row = tid >> 5;          // 0..7
    const int b_c4  = (tid & 31) * 4;    // 0..124

    const float* Aptr = A + (size_t)(bm + a_row) * K + a_c4;
    const float* Bptr = Bm + (size_t)b_row * N + bn + b_c4;

    for (int k0 = 0; k0 < K; k0 += 8) {
        float4 av = *(const float4*)(Aptr + k0);
        As[a_c4 + 0][a_row] = av.x;
        As[a_c4 + 1][a_row] = av.y;
        As[a_c4 + 2][a_row] = av.z;
        As[a_c4 + 3][a_row] = av.w;
        float4 bv = *(const float4*)(Bptr + (size_t)k0 * N);
        *(float4*)&Bs[b_row][b_c4] = bv;
        __syncthreads();

#pragma unroll
        for (int k = 0; k < 8; ++k) {
            float4 a0 = *(const float4*)&As[k][ty * 4];
            float4 a1 = *(const float4*)&As[k][64 + ty * 4];
            float4 b0 = *(const float4*)&Bs[k][tx * 4];
            float4 b1 = *(const float4*)&Bs[k][64 + tx * 4];
            float af[8] = {a0.x, a0.y, a0.z, a0.w, a1.x, a1.y, a1.z, a1.w};
            float bf[8] = {b0.x, b0.y, b0.z, b0.w, b1.x, b1.y, b1.z, b1.w};
#pragma unroll
            for (int i = 0; i < 8; i++)
#pragma unroll
                for (int j = 0; j < 8; j++)
                    acc[i][j] = fmaf(af[i], bf[j], acc[i][j]);
        }
        __syncthreads();
    }

    // epilogue
#pragma unroll
    for (int i = 0; i < 8; i++) {
        const int r = bm + ((i < 4) ? (ty * 4 + i) : (64 + ty * 4 + (i - 4)));
#pragma unroll
        for (int jj = 0; jj < 2; jj++) {
            const int c = bn + ((jj == 0) ? (tx * 4) : (64 + tx * 4));
            float4 o;
            o.x = acc[i][jj * 4 + 0];
            o.y = acc[i][jj * 4 + 1];
            o.z = acc[i][jj * 4 + 2];
            o.w = acc[i][jj * 4 + 3];
            if (EPI >= 1) {
                float4 bv4 = *(const float4*)&bias[c];
                o.x += bv4.x; o.y += bv4.y; o.z += bv4.z; o.w += bv4.w;
            }
            if (EPI == 2) {
                o.x = gelu_exact(o.x); o.y = gelu_exact(o.y);
                o.z = gelu_exact(o.z); o.w = gelu_exact(o.w);
            }
            *(float4*)&C[(size_t)r * N + c] = o;
        }
    }
}

// ---------------- Flash attention ------------------------------------------
// One block per (q-tile of 64, b*h). HD=64. 256 threads; each thread owns a
// 4x4 patch of the 64x64 score tile (rows ty*4.., cols tx*4..).
static constexpr int FS = 65;                        // padded smem row stride
static constexpr int FLASH_SMEM = 4 * 64 * FS * 4;   // Qs,Ks,Vs,Ps

__global__ __launch_bounds__(256) void flash_kernel(
    const float* __restrict__ Qb, const float* __restrict__ Kb,
    const float* __restrict__ Vb, float* __restrict__ Ob)
{
    extern __shared__ float sm[];
    float* Qs = sm;
    float* Ks = sm + 64 * FS;
    float* Vs = sm + 2 * 64 * FS;
    float* Ps = sm + 3 * 64 * FS;

    const int tid = threadIdx.x;
    const int tx = tid & 15;
    const int ty = tid >> 4;
    const int bh = blockIdx.y;
    const int b = bh / Hh;
    const int h = bh % Hh;
    const int q0 = blockIdx.x * 64;

    const float scale = 0.125f;   // 64^-0.5

    // load Q tile [64 x 64]
    {
        const size_t baseQ = ((size_t)(b * Tt + q0)) * Dd + h * HDd;
        for (int i = tid; i < 64 * 16; i += 256) {
            int r = i >> 4, c4 = (i & 15) << 2;
            float4 v = *(const float4*)&Qb[baseQ + (size_t)r * Dd + c4];
            Qs[r * FS + c4 + 0] = v.x;
            Qs[r * FS + c4 + 1] = v.y;
            Qs[r * FS + c4 + 2] = v.z;
            Qs[r * FS + c4 + 3] = v.w;
        }
    }

    float acc[4][4];
    float mi[4], li[4];
#pragma unroll
    for (int i = 0; i < 4; i++) {
        mi[i] = -INFINITY;
        li[i] = 0.0f;
#pragma unroll
        for (int j = 0; j < 4; j++) acc[i][j] = 0.0f;
    }

    for (int kv0 = 0; kv0 < Tt; kv0 += 64) {
        // load K,V tiles
        const size_t baseK = ((size_t)(b * Tt + kv0)) * Dd + h * HDd;
        for (int i = tid; i < 64 * 16; i += 256) {
            int r = i >> 4, c4 = (i & 15) << 2;
            float4 kv = *(const float4*)&Kb[baseK + (size_t)r * Dd + c4];
            Ks[r * FS + c4 + 0] = kv.x;
            Ks[r * FS + c4 + 1] = kv.y;
            Ks[r * FS + c4 + 2] = kv.z;
            Ks[r * FS + c4 + 3] = kv.w;
            float4 vv = *(const float4*)&Vb[baseK + (size_t)r * Dd + c4];
            Vs[r * FS + c4 + 0] = vv.x;
            Vs[r * FS + c4 + 1] = vv.y;
            Vs[r * FS + c4 + 2] = vv.z;
            Vs[r * FS + c4 + 3] = vv.w;
        }
        __syncthreads();

        // S = Q K^T  (thread's 4x4 patch)
        float s[4][4];
#pragma unroll
        for (int i = 0; i < 4; i++)
#pragma unroll
            for (int j = 0; j < 4; j++) s[i][j] = 0.0f;

        for (int c = 0; c < 64; ++c) {
            float qf[4], kf[4];
#pragma unroll
            for (int i = 0; i < 4; i++) qf[i] = Qs[(ty * 4 + i) * FS + c];
#pragma unroll
            for (int j = 0; j < 4; j++) kf[j] = Ks[(tx * 4 + j) * FS + c];
#pragma unroll
            for (int i = 0; i < 4; i++)
#pragma unroll
                for (int j = 0; j < 4; j++)
                    s[i][j] = fmaf(qf[i], kf[j], s[i][j]);
        }

        // online softmax update per row
#pragma unroll
        for (int i = 0; i < 4; i++) {
            float sc[4];
            float rm = -INFINITY;
#pragma unroll
            for (int j = 0; j < 4; j++) {
                sc[j] = s[i][j] * scale;
                rm = fmaxf(rm, sc[j]);
            }
            // reduce max over the 16 lanes of this row group
#pragma unroll
            for (int o = 8; o > 0; o >>= 1)
                rm = fmaxf(rm, __shfl_xor_sync(0xffffffffu, rm, o));
            float mnew = fmaxf(mi[i], rm);
            float p[4], rs = 0.0f;
#pragma unroll
            for (int j = 0; j < 4; j++) {
                p[j] = expf(sc[j] - mnew);
                rs += p[j];
            }
#pragma unroll
            for (int o = 8; o > 0; o >>= 1)
                rs += __shfl_xor_sync(0xffffffffu, rs, o);
            float alpha = expf(mi[i] - mnew);
            li[i] = li[i] * alpha + rs;
            mi[i] = mnew;
#pragma unroll
            for (int j = 0; j < 4; j++) {
                acc[i][j] *= alpha;
                Ps[(ty * 4 + i) * FS + tx * 4 + j] = p[j];
            }
        }
        __syncthreads();

        // O += P @ V
        for (int k = 0; k < 64; ++k) {
            float pf[4], vf[4];
#pragma unroll
            for (int i = 0; i < 4; i++) pf[i] = Ps[(ty * 4 + i) * FS + k];
#pragma unroll
            for (int j = 0; j < 4; j++) vf[j] = Vs[k * FS + tx * 4 + j];
#pragma unroll
            for (int i = 0; i < 4; i++)
#pragma unroll
                for (int j = 0; j < 4; j++)
                    acc[i][j] = fmaf(pf[i], vf[j], acc[i][j]);
        }
        __syncthreads();   // before next tile overwrites Ks/Vs
    }

    // normalize + write (already in [B,T,H*HD] layout)
#pragma unroll
    for (int i = 0; i < 4; i++) {
        const float inv = 1.0f / li[i];
        const int r = q0 + ty * 4 + i;
        const size_t baseO = ((size_t)(b * Tt + r)) * Dd + h * HDd;
#pragma unroll
        for (int j = 0; j < 4; j++)
            Ob[baseO + tx * 4 + j] = acc[i][j] * inv;
    }
}

// ---------------- residual add + LayerNorm ---------------------------------
__device__ __forceinline__ float block_sum_1024(float v, float* red) {
    const int tid = threadIdx.x;
    __syncthreads();   // protect red reuse across calls
#pragma unroll
    for (int o = 16; o > 0; o >>= 1)
        v += __shfl_xor_sync(0xffffffffu, v, o);
    if ((tid & 31) == 0) red[tid >> 5] = v;
    __syncthreads();
    float t = (tid < 8) ? red[tid] : 0.0f;
    if (tid < 32) {
#pragma unroll
        for (int o = 4; o > 0; o >>= 1)
            t += __shfl_xor_sync(0xffffffffu, t, o);
        if (tid == 0) red[0] = t;
    }
    __syncthreads();
    return red[0];
}

__global__ __launch_bounds__(256) void add_ln_kernel(
    const float* __restrict__ A, const float* __restrict__ Bv,
    const float* __restrict__ g, const float* __restrict__ be,
    float* __restrict__ out)
{
    __shared__ float red[8];
    const int row = blockIdx.x;
    const int tid = threadIdx.x;
    const size_t base = (size_t)row * Dd;
    const int c = tid * 4;

    float4 a = *(const float4*)&A[base + c];
    float4 b = *(const float4*)&Bv[base + c];
    float v0 = a.x + b.x, v1 = a.y + b.y, v2 = a.z + b.z, v3 = a.w + b.w;

    float s = block_sum_1024(v0 + v1 + v2 + v3, red);
    const float mu = s * (1.0f / Dd);
    float d0 = v0 - mu, d1 = v1 - mu, d2 = v2 - mu, d3 = v3 - mu;
    float q = block_sum_1024(d0 * d0 + d1 * d1 + d2 * d2 + d3 * d3, red);
    const float inv = rsqrtf(q * (1.0f / Dd) + 1e-5f);

    float4 gv = *(const float4*)&g[c];
    float4 bev = *(const float4*)&be[c];
    float4 o;
    o.x = d0 * inv * gv.x + bev.x;
    o.y = d1 * inv * gv.y + bev.y;
    o.z = d2 * inv * gv.z + bev.z;
    o.w = d3 * inv * gv.w + bev.w;
    *(float4*)&out[base + c] = o;
}

// ---------------- orchestration --------------------------------------------
extern "C" void kernel_launch(void* const* d_in, const int* in_sizes, int n_in,
                              void* d_out, int out_size)
{
    const float* x   = (const float*)d_in[0];
    const float* wq  = (const float*)d_in[1];
    const float* wk  = (const float*)d_in[2];
    const float* wv  = (const float*)d_in[3];
    const float* wo  = (const float*)d_in[4];
    const float* w1  = (const float*)d_in[5];
    const float* b1  = (const float*)d_in[6];
    const float* w2  = (const float*)d_in[7];
    const float* b2  = (const float*)d_in[8];
    const float* g1  = (const float*)d_in[9];
    const float* be1 = (const float*)d_in[10];
    const float* g2  = (const float*)d_in[11];
    const float* be2 = (const float*)d_in[12];

    float *Q, *K, *V, *attn, *proj, *h, *ff1, *ff2;
    cudaGetSymbolAddress((void**)&Q,    g_Q);
    cudaGetSymbolAddress((void**)&K,    g_K);
    cudaGetSymbolAddress((void**)&V,    g_V);
    cudaGetSymbolAddress((void**)&attn, g_attn);
    cudaGetSymbolAddress((void**)&proj, g_proj);
    cudaGetSymbolAddress((void**)&h,    g_h);
    cudaGetSymbolAddress((void**)&ff1,  g_ff1);
    cudaGetSymbolAddress((void**)&ff2,  g_ff2);

    cudaFuncSetAttribute(flash_kernel,
                         cudaFuncAttributeMaxDynamicSharedMemorySize, FLASH_SMEM);

    const dim3 blk(256);
    const dim3 gD (Dd  / 128, Mrows / 128);   // N=1024 grids
    const dim3 gDF(DFf / 128, Mrows / 128);   // N=4096 grid

    // QKV projections
    gemm_kernel<0><<<gD, blk>>>(x, wq, nullptr, Q, Mrows, Dd, Dd);
    gemm_kernel<0><<<gD, blk>>>(x, wk, nullptr, K, Mrows, Dd, Dd);
    gemm_kernel<0><<<gD, blk>>>(x, wv, nullptr, V, Mrows, Dd, Dd);

    // attention
    flash_kernel<<<dim3(Tt / 64, Bb * Hh), blk, FLASH_SMEM>>>(Q, K, V, attn);

    // output projection
    gemm_kernel<0><<<gD, blk>>>(attn, wo, nullptr, proj, Mrows, Dd, Dd);

    // h = LN(x + attn_proj)
    add_ln_kernel<<<Mrows, blk>>>(x, proj, g1, be1, h);

    // FFN
    gemm_kernel<2><<<gDF, blk>>>(h, w1, b1, ff1, Mrows, DFf, Dd);
    gemm_kernel<1><<<gD,  blk>>>(ff1, w2, b2, ff2, Mrows, Dd, DFf);

    // out = LN(h + ff)
    add_ln_kernel<<<Mrows, blk>>>(h, ff2, g2, be2, (float*)d_out);
}

// round 2
// speedup vs baseline: 1.7586x; 1.7586x over previous
#include <cuda_runtime.h>
#include <math.h>
#include <stdint.h>

// Problem shape (fixed)
static constexpr int Bb = 4;
static constexpr int Tt = 2048;
static constexpr int Dd = 1024;
static constexpr int Hh = 16;
static constexpr int HDd = 64;
static constexpr int DFf = 4096;
static constexpr int Mrows = Bb * Tt;   // 8192

// ---------------- scratch (device globals; no allocation allowed) ----------
__device__ float g_Q[(size_t)Mrows * Dd];
__device__ float g_K[(size_t)Mrows * Dd];
__device__ float g_V[(size_t)Mrows * Dd];
__device__ float g_attn[(size_t)Mrows * Dd];
__device__ float g_proj[(size_t)Mrows * Dd];
__device__ float g_h[(size_t)Mrows * Dd];
__device__ float g_ff1[(size_t)Mrows * DFf];
__device__ float g_ff2[(size_t)Mrows * Dd];

// ---------------- helpers ----------------
__device__ __forceinline__ float gelu_exact(float x) {
    return 0.5f * x * (1.0f + erff(x * 0.70710678118654752f));
}

__device__ __forceinline__ uint32_t f2tf32(float f) {
    uint32_t u;
    asm("cvt.rna.tf32.f32 %0, %1;" : "=r"(u) : "f"(f));
    return u;
}

__device__ __forceinline__ void mma_tf32(
    float& c0, float& c1, float& c2, float& c3,
    uint32_t a0, uint32_t a1, uint32_t a2, uint32_t a3,
    uint32_t b0, uint32_t b1)
{
    asm volatile(
        "mma.sync.aligned.m16n8k8.row.col.f32.tf32.tf32.f32 "
        "{%0,%1,%2,%3}, {%4,%5,%6,%7}, {%8,%9}, {%0,%1,%2,%3};\n"
        : "+f"(c0), "+f"(c1), "+f"(c2), "+f"(c3)
        : "r"(a0), "r"(a1), "r"(a2), "r"(a3), "r"(b0), "r"(b1));
}

// ---------------- tf32 tensor-core GEMM ------------------------------------
// C[M,N] = A[M,K] @ B[K,N] (+bias)(+gelu)
// Block tile 128x128, BK=16, 256 threads (8 warps), warp tile 64x32.
// mma.sync m16n8k8 tf32. Double-buffered smem, fp32->tf32 at smem store.
// As layout: [m][k] stride 20  (bank-conflict-free frag loads, 16B-aligned STS.128)
// Bs layout: [k][n] stride 136 (same properties)
static constexpr int AS_STRIDE = 20;    // 16 k + 4 pad
static constexpr int BS_STRIDE = 136;   // 128 n + 8 pad

template <int EPI>
__global__ __launch_bounds__(256) void gemm_tc_kernel(
    const float* __restrict__ A, const float* __restrict__ Bm,
    const float* __restrict__ bias, float* __restrict__ C,
    int M, int N, int K)
{
    __shared__ uint32_t As[2][128 * AS_STRIDE];
    __shared__ uint32_t Bs[2][16 * BS_STRIDE];

    const int tid = threadIdx.x;
    const int warp = tid >> 5;
    const int lane = tid & 31;
    const int lq = lane >> 2;   // 0..7
    const int lr = lane & 3;    // 0..3

    const int bm = blockIdx.y * 128;
    const int bn = blockIdx.x * 128;
    const int wm = (warp & 1) * 64;        // warp m offset in block
    const int wn = (warp >> 1) * 32;       // warp n offset in block

    // Global load assignments
    // A tile: 128 rows x 16 cols = 512 float4; thread does ids {tid, tid+256}
    // B tile: 16 rows x 128 cols = 512 float4; same ids
    const int a_row0 = tid >> 2;              // for id=tid        (0..63)
    const int a_row1 = (tid + 256) >> 2;      // (64..127)
    const int a_c4   = (tid & 3) * 4;
    const int b_row0 = tid >> 5;              // 0..7
    const int b_row1 = (tid + 256) >> 5;      // 8..15
    const int b_n4   = (tid & 31) * 4;

    const float* Ag = A + (size_t)(bm) * K;
    const float* Bg = Bm + bn;

    float acc[4][4][4];
#pragma unroll
    for (int i = 0; i < 4; i++)
#pragma unroll
        for (int j = 0; j < 4; j++)
#pragma unroll
            for (int r = 0; r < 4; r++) acc[i][j][r] = 0.0f;

    // ---- load first tile into buffer 0 ----
    {
        float4 av0 = *(const float4*)(Ag + (size_t)a_row0 * K + a_c4);
        float4 av1 = *(const float4*)(Ag + (size_t)a_row1 * K + a_c4);
        float4 bv0 = *(const float4*)(Bg + (size_t)b_row0 * N + b_n4);
        float4 bv1 = *(const float4*)(Bg + (size_t)b_row1 * N + b_n4);
        uint32_t* asp0 = &As[0][a_row0 * AS_STRIDE + a_c4];
        asp0[0] = f2tf32(av0.x); asp0[1] = f2tf32(av0.y);
        asp0[2] = f2tf32(av0.z); asp0[3] = f2tf32(av0.w);
        uint32_t* asp1 = &As[0][a_row1 * AS_STRIDE + a_c4];
        asp1[0] = f2tf32(av1.x); asp1[1] = f2tf32(av1.y);
        asp1[2] = f2tf32(av1.z); asp1[3] = f2tf32(av1.w);
        uint32_t* bsp0 = &Bs[0][b_row0 * BS_STRIDE + b_n4];
        bsp0[0] = f2tf32(bv0.x); bsp0[1] = f2tf32(bv0.y);
        bsp0[2] = f2tf32(bv0.z); bsp0[3] = f2tf32(bv0.w);
        uint32_t* bsp1 = &Bs[0][b_row1 * BS_STRIDE + b_n4];
        bsp1[0] = f2tf32(bv1.x); bsp1[1] = f2tf32(bv1.y);
        bsp1[2] = f2tf32(bv1.z); bsp1[3] = f2tf32(bv1.w);
    }
    __syncthreads();

    int buf = 0;
    for (int k0 = 0; k0 < K; k0 += 16) {
        const bool has_next = (k0 + 16) < K;
        float4 av0, av1, bv0, bv1;
        if (has_next) {
            const int kn = k0 + 16;
            av0 = *(const float4*)(Ag + (size_t)a_row0 * K + kn + a_c4);
            av1 = *(const float4*)(Ag + (size_t)a_row1 * K + kn + a_c4);
            bv0 = *(const float4*)(Bg + (size_t)(kn + b_row0) * N + b_n4);
            bv1 = *(const float4*)(Bg + (size_t)(kn + b_row1) * N + b_n4);
        }

        const uint32_t* Asb = As[buf];
        const uint32_t* Bsb = Bs[buf];
#pragma unroll
        for (int kk = 0; kk < 16; kk += 8) {
            uint32_t af[4][4];
#pragma unroll
            for (int mt = 0; mt < 4; mt++) {
                const int r0 = wm + mt * 16 + lq;
                af[mt][0] = Asb[r0 * AS_STRIDE + kk + lr];
                af[mt][1] = Asb[(r0 + 8) * AS_STRIDE + kk + lr];
                af[mt][2] = Asb[r0 * AS_STRIDE + kk + lr + 4];
                af[mt][3] = Asb[(r0 + 8) * AS_STRIDE + kk + lr + 4];
            }
            uint32_t bf[4][2];
#pragma unroll
            for (int nt = 0; nt < 4; nt++) {
                const int c0 = wn + nt * 8 + lq;
                bf[nt][0] = Bsb[(kk + lr) * BS_STRIDE + c0];
                bf[nt][1] = Bsb[(kk + lr + 4) * BS_STRIDE + c0];
            }
#pragma unroll
            for (int mt = 0; mt < 4; mt++)
#pragma unroll
                for (int nt = 0; nt < 4; nt++)
                    mma_tf32(acc[mt][nt][0], acc[mt][nt][1],
                             acc[mt][nt][2], acc[mt][nt][3],
                             af[mt][0], af[mt][1], af[mt][2], af[mt][3],
                             bf[nt][0], bf[nt][1]);
        }

        if (has_next) {
            const int nb = buf ^ 1;
            uint32_t* asp0 = &As[nb][a_row0 * AS_STRIDE + a_c4];
            asp0[0] = f2tf32(av0.x); asp0[1] = f2tf32(av0.y);
            asp0[2] = f2tf32(av0.z); asp0[3] = f2tf32(av0.w);
            uint32_t* asp1 = &As[nb][a_row1 * AS_STRIDE + a_c4];
            asp1[0] = f2tf32(av1.x); asp1[1] = f2tf32(av1.y);
            asp1[2] = f2tf32(av1.z); asp1[3] = f2tf32(av1.w);
            uint32_t* bsp0 = &Bs[nb][b_row0 * BS_STRIDE + b_n4];
            bsp0[0] = f2tf32(bv0.x); bsp0[1] = f2tf32(bv0.y);
            bsp0[2] = f2tf32(bv0.z); bsp0[3] = f2tf32(bv0.w);
            uint32_t* bsp1 = &Bs[nb][b_row1 * BS_STRIDE + b_n4];
            bsp1[0] = f2tf32(bv1.x); bsp1[1] = f2tf32(bv1.y);
            bsp1[2] = f2tf32(bv1.z); bsp1[3] = f2tf32(bv1.w);
            __syncthreads();
            buf = nb;
        }
    }

    // ---- epilogue ----
    // c0: (row, col) = (lq, 2*lr) ; c1: col+1 ; c2: row+8 ; c3: row+8,col+1
#pragma unroll
    for (int mt = 0; mt < 4; mt++) {
#pragma unroll
        for (int nt = 0; nt < 4; nt++) {
            const int col = bn + wn + nt * 8 + 2 * lr;
#pragma unroll
            for (int half = 0; half < 2; half++) {
                const int row = bm + wm + mt * 16 + lq + half * 8;
                float v0 = acc[mt][nt][half * 2 + 0];
                float v1 = acc[mt][nt][half * 2 + 1];
                if (EPI >= 1) {
                    v0 += bias[col];
                    v1 += bias[col + 1];
                }
                if (EPI == 2) {
                    v0 = gelu_exact(v0);
                    v1 = gelu_exact(v1);
                }
                float2 o = make_float2(v0, v1);
                *(float2*)&C[(size_t)row * N + col] = o;
            }
        }
    }
}

// ---------------- Flash attention (unchanged SIMT) --------------------------
static constexpr int FS = 65;
static constexpr int FLASH_SMEM = 4 * 64 * FS * 4;

__global__ __launch_bounds__(256) void flash_kernel(
    const float* __restrict__ Qb, const float* __restrict__ Kb,
    const float* __restrict__ Vb, float* __restrict__ Ob)
{
    extern __shared__ float sm[];
    float* Qs = sm;
    float* Ks = sm + 64 * FS;
    float* Vs = sm + 2 * 64 * FS;
    float* Ps = sm + 3 * 64 * FS;

    const int tid = threadIdx.x;
    const int tx = tid & 15;
    const int ty = tid >> 4;
    const int bh = blockIdx.y;
    const int b = bh / Hh;
    const int h = bh % Hh;
    const int q0 = blockIdx.x * 64;

    const float scale = 0.125f;

    {
        const size_t baseQ = ((size_t)(b * Tt + q0)) * Dd + h * HDd;
        for (int i = tid; i < 64 * 16; i += 256) {
            int r = i >> 4, c4 = (i & 15) << 2;
            float4 v = *(const float4*)&Qb[baseQ + (size_t)r * Dd + c4];
            Qs[r * FS + c4 + 0] = v.x;
            Qs[r * FS + c4 + 1] = v.y;
            Qs[r * FS + c4 + 2] = v.z;
            Qs[r * FS + c4 + 3] = v.w;
        }
    }

    float acc[4][4];
    float mi[4], li[4];
#pragma unroll
    for (int i = 0; i < 4; i++) {
        mi[i] = -INFINITY;
        li[i] = 0.0f;
#pragma unroll
        for (int j = 0; j < 4; j++) acc[i][j] = 0.0f;
    }

    for (int kv0 = 0; kv0 < Tt; kv0 += 64) {
        const size_t baseK = ((size_t)(b * Tt + kv0)) * Dd + h * HDd;
        for (int i = tid; i < 64 * 16; i += 256) {
            int r = i >> 4, c4 = (i & 15) << 2;
            float4 kv = *(const float4*)&Kb[baseK + (size_t)r * Dd + c4];
            Ks[r * FS + c4 + 0] = kv.x;
            Ks[r * FS + c4 + 1] = kv.y;
            Ks[r * FS + c4 + 2] = kv.z;
            Ks[r * FS + c4 + 3] = kv.w;
            float4 vv = *(const float4*)&Vb[baseK + (size_t)r * Dd + c4];
            Vs[r * FS + c4 + 0] = vv.x;
            Vs[r * FS + c4 + 1] = vv.y;
            Vs[r * FS + c4 + 2] = vv.z;
            Vs[r * FS + c4 + 3] = vv.w;
        }
        __syncthreads();

        float s[4][4];
#pragma unroll
        for (int i = 0; i < 4; i++)
#pragma unroll
            for (int j = 0; j < 4; j++) s[i][j] = 0.0f;

        for (int c = 0; c < 64; ++c) {
            float qf[4], kf[4];
#pragma unroll
            for (int i = 0; i < 4; i++) qf[i] = Qs[(ty * 4 + i) * FS + c];
#pragma unroll
            for (int j = 0; j < 4; j++) kf[j] = Ks[(tx * 4 + j) * FS + c];
#pragma unroll
            for (int i = 0; i < 4; i++)
#pragma unroll
                for (int j = 0; j < 4; j++)
                    s[i][j] = fmaf(qf[i], kf[j], s[i][j]);
        }

#pragma unroll
        for (int i = 0; i < 4; i++) {
            float sc[4];
            float rm = -INFINITY;
#pragma unroll
            for (int j = 0; j < 4; j++) {
                sc[j] = s[i][j] * scale;
                rm = fmaxf(rm, sc[j]);
            }
#pragma unroll
            for (int o = 8; o > 0; o >>= 1)
                rm = fmaxf(rm, __shfl_xor_sync(0xffffffffu, rm, o));
            float mnew = fmaxf(mi[i], rm);
            float p[4], rs = 0.0f;
#pragma unroll
            for (int j = 0; j < 4; j++) {
                p[j] = expf(sc[j] - mnew);
                rs += p[j];
            }
#pragma unroll
            for (int o = 8; o > 0; o >>= 1)
                rs += __shfl_xor_sync(0xffffffffu, rs, o);
            float alpha = expf(mi[i] - mnew);
            li[i] = li[i] * alpha + rs;
            mi[i] = mnew;
#pragma unroll
            for (int j = 0; j < 4; j++) {
                acc[i][j] *= alpha;
                Ps[(ty * 4 + i) * FS + tx * 4 + j] = p[j];
            }
        }
        __syncthreads();

        for (int k = 0; k < 64; ++k) {
            float pf[4], vf[4];
#pragma unroll
            for (int i = 0; i < 4; i++) pf[i] = Ps[(ty * 4 + i) * FS + k];
#pragma unroll
            for (int j = 0; j < 4; j++) vf[j] = Vs[k * FS + tx * 4 + j];
#pragma unroll
            for (int i = 0; i < 4; i++)
#pragma unroll
                for (int j = 0; j < 4; j++)
                    acc[i][j] = fmaf(pf[i], vf[j], acc[i][j]);
        }
        __syncthreads();
    }

#pragma unroll
    for (int i = 0; i < 4; i++) {
        const float inv = 1.0f / li[i];
        const int r = q0 + ty * 4 + i;
        const size_t baseO = ((size_t)(b * Tt + r)) * Dd + h * HDd;
#pragma unroll
        for (int j = 0; j < 4; j++)
            Ob[baseO + tx * 4 + j] = acc[i][j] * inv;
    }
}

// ---------------- residual add + LayerNorm ---------------------------------
__device__ __forceinline__ float block_sum_1024(float v, float* red) {
    const int tid = threadIdx.x;
    __syncthreads();
#pragma unroll
    for (int o = 16; o > 0; o >>= 1)
        v += __shfl_xor_sync(0xffffffffu, v, o);
    if ((tid & 31) == 0) red[tid >> 5] = v;
    __syncthreads();
    float t = (tid < 8) ? red[tid] : 0.0f;
    if (tid < 32) {
#pragma unroll
        for (int o = 4; o > 0; o >>= 1)
            t += __shfl_xor_sync(0xffffffffu, t, o);
        if (tid == 0) red[0] = t;
    }
    __syncthreads();
    return red[0];
}

__global__ __launch_bounds__(256) void add_ln_kernel(
    const float* __restrict__ A, const float* __restrict__ Bv,
    const float* __restrict__ g, const float* __restrict__ be,
    float* __restrict__ out)
{
    __shared__ float red[8];
    const int row = blockIdx.x;
    const int tid = threadIdx.x;
    const size_t base = (size_t)row * Dd;
    const int c = tid * 4;

    float4 a = *(const float4*)&A[base + c];
    float4 b = *(const float4*)&Bv[base + c];
    float v0 = a.x + b.x, v1 = a.y + b.y, v2 = a.z + b.z, v3 = a.w + b.w;

    float s = block_sum_1024(v0 + v1 + v2 + v3, red);
    const float mu = s * (1.0f / Dd);
    float d0 = v0 - mu, d1 = v1 - mu, d2 = v2 - mu, d3 = v3 - mu;
    float q = block_sum_1024(d0 * d0 + d1 * d1 + d2 * d2 + d3 * d3, red);
    const float inv = rsqrtf(q * (1.0f / Dd) + 1e-5f);

    float4 gv = *(const float4*)&g[c];
    float4 bev = *(const float4*)&be[c];
    float4 o;
    o.x = d0 * inv * gv.x + bev.x;
    o.y = d1 * inv * gv.y + bev.y;
    o.z = d2 * inv * gv.z + bev.z;
    o.w = d3 * inv * gv.w + bev.w;
    *(float4*)&out[base + c] = o;
}

// ---------------- orchestration --------------------------------------------
extern "C" void kernel_launch(void* const* d_in, const int* in_sizes, int n_in,
                              void* d_out, int out_size)
{
    const float* x   = (const float*)d_in[0];
    const float* wq  = (const float*)d_in[1];
    const float* wk  = (const float*)d_in[2];
    const float* wv  = (const float*)d_in[3];
    const float* wo  = (const float*)d_in[4];
    const float* w1  = (const float*)d_in[5];
    const float* b1  = (const float*)d_in[6];
    const float* w2  = (const float*)d_in[7];
    const float* b2  = (const float*)d_in[8];
    const float* g1  = (const float*)d_in[9];
    const float* be1 = (const float*)d_in[10];
    const float* g2  = (const float*)d_in[11];
    const float* be2 = (const float*)d_in[12];

    float *Q, *K, *V, *attn, *proj, *h, *ff1, *ff2;
    cudaGetSymbolAddress((void**)&Q,    g_Q);
    cudaGetSymbolAddress((void**)&K,    g_K);
    cudaGetSymbolAddress((void**)&V,    g_V);
    cudaGetSymbolAddress((void**)&attn, g_attn);
    cudaGetSymbolAddress((void**)&proj, g_proj);
    cudaGetSymbolAddress((void**)&h,    g_h);
    cudaGetSymbolAddress((void**)&ff1,  g_ff1);
    cudaGetSymbolAddress((void**)&ff2,  g_ff2);

    cudaFuncSetAttribute(flash_kernel,
                         cudaFuncAttributeMaxDynamicSharedMemorySize, FLASH_SMEM);

    const dim3 blk(256);
    const dim3 gD (Dd  / 128, Mrows / 128);
    const dim3 gDF(DFf / 128, Mrows / 128);

    gemm_tc_kernel<0><<<gD, blk>>>(x, wq, nullptr, Q, Mrows, Dd, Dd);
    gemm_tc_kernel<0><<<gD, blk>>>(x, wk, nullptr, K, Mrows, Dd, Dd);
    gemm_tc_kernel<0><<<gD, blk>>>(x, wv, nullptr, V, Mrows, Dd, Dd);

    flash_kernel<<<dim3(Tt / 64, Bb * Hh), blk, FLASH_SMEM>>>(Q, K, V, attn);

    gemm_tc_kernel<0><<<gD, blk>>>(attn, wo, nullptr, proj, Mrows, Dd, Dd);

    add_ln_kernel<<<Mrows, blk>>>(x, proj, g1, be1, h);

    gemm_tc_kernel<2><<<gDF, blk>>>(h, w1, b1, ff1, Mrows, DFf, Dd);
    gemm_tc_kernel<1><<<gD,  blk>>>(ff1, w2, b2, ff2, Mrows, Dd, DFf);

    add_ln_kernel<<<Mrows, blk>>>(h, ff2, g2, be2, (float*)d_out);
}

// round 3
// speedup vs baseline: 2.8515x; 1.6215x over previous
#include <cuda_runtime.h>
#include <math.h>
#include <stdint.h>

// Problem shape (fixed)
static constexpr int Bb = 4;
static constexpr int Tt = 2048;
static constexpr int Dd = 1024;
static constexpr int Hh = 16;
static constexpr int HDd = 64;
static constexpr int DFf = 4096;
static constexpr int Mrows = Bb * Tt;   // 8192

// ---------------- scratch (device globals; no allocation allowed) ----------
__device__ float g_Q[(size_t)Mrows * Dd];
__device__ float g_K[(size_t)Mrows * Dd];
__device__ float g_V[(size_t)Mrows * Dd];
__device__ float g_attn[(size_t)Mrows * Dd];
__device__ float g_proj[(size_t)Mrows * Dd];
__device__ float g_h[(size_t)Mrows * Dd];
__device__ float g_ff1[(size_t)Mrows * DFf];
__device__ float g_ff2[(size_t)Mrows * Dd];

// ---------------- helpers ----------------
__device__ __forceinline__ float gelu_exact(float x) {
    return 0.5f * x * (1.0f + erff(x * 0.70710678118654752f));
}

__device__ __forceinline__ uint32_t f2tf32(float f) {
    uint32_t u;
    asm("cvt.rna.tf32.f32 %0, %1;" : "=r"(u) : "f"(f));
    return u;
}

__device__ __forceinline__ void mma_tf32(
    float& c0, float& c1, float& c2, float& c3,
    uint32_t a0, uint32_t a1, uint32_t a2, uint32_t a3,
    uint32_t b0, uint32_t b1)
{
    asm volatile(
        "mma.sync.aligned.m16n8k8.row.col.f32.tf32.tf32.f32 "
        "{%0,%1,%2,%3}, {%4,%5,%6,%7}, {%8,%9}, {%0,%1,%2,%3};\n"
        : "+f"(c0), "+f"(c1), "+f"(c2), "+f"(c3)
        : "r"(a0), "r"(a1), "r"(a2), "r"(a3), "r"(b0), "r"(b1));
}

// ---------------- tf32 tensor-core GEMM ------------------------------------
static constexpr int AS_STRIDE = 20;    // 16 k + 4 pad
static constexpr int BS_STRIDE = 136;   // 128 n + 8 pad

template <int EPI>
__global__ __launch_bounds__(256) void gemm_tc_kernel(
    const float* __restrict__ A, const float* __restrict__ Bm,
    const float* __restrict__ bias, float* __restrict__ C,
    int M, int N, int K)
{
    __shared__ uint32_t As[2][128 * AS_STRIDE];
    __shared__ uint32_t Bs[2][16 * BS_STRIDE];

    const int tid = threadIdx.x;
    const int warp = tid >> 5;
    const int lane = tid & 31;
    const int lq = lane >> 2;
    const int lr = lane & 3;

    const int bm = blockIdx.y * 128;
    const int bn = blockIdx.x * 128;
    const int wm = (warp & 1) * 64;
    const int wn = (warp >> 1) * 32;

    const int a_row0 = tid >> 2;
    const int a_row1 = (tid + 256) >> 2;
    const int a_c4   = (tid & 3) * 4;
    const int b_row0 = tid >> 5;
    const int b_row1 = (tid + 256) >> 5;
    const int b_n4   = (tid & 31) * 4;

    const float* Ag = A + (size_t)(bm) * K;
    const float* Bg = Bm + bn;

    float acc[4][4][4];
#pragma unroll
    for (int i = 0; i < 4; i++)
#pragma unroll
        for (int j = 0; j < 4; j++)
#pragma unroll
            for (int r = 0; r < 4; r++) acc[i][j][r] = 0.0f;

    {
        float4 av0 = *(const float4*)(Ag + (size_t)a_row0 * K + a_c4);
        float4 av1 = *(const float4*)(Ag + (size_t)a_row1 * K + a_c4);
        float4 bv0 = *(const float4*)(Bg + (size_t)b_row0 * N + b_n4);
        float4 bv1 = *(const float4*)(Bg + (size_t)b_row1 * N + b_n4);
        uint32_t* asp0 = &As[0][a_row0 * AS_STRIDE + a_c4];
        asp0[0] = f2tf32(av0.x); asp0[1] = f2tf32(av0.y);
        asp0[2] = f2tf32(av0.z); asp0[3] = f2tf32(av0.w);
        uint32_t* asp1 = &As[0][a_row1 * AS_STRIDE + a_c4];
        asp1[0] = f2tf32(av1.x); asp1[1] = f2tf32(av1.y);
        asp1[2] = f2tf32(av1.z); asp1[3] = f2tf32(av1.w);
        uint32_t* bsp0 = &Bs[0][b_row0 * BS_STRIDE + b_n4];
        bsp0[0] = f2tf32(bv0.x); bsp0[1] = f2tf32(bv0.y);
        bsp0[2] = f2tf32(bv0.z); bsp0[3] = f2tf32(bv0.w);
        uint32_t* bsp1 = &Bs[0][b_row1 * BS_STRIDE + b_n4];
        bsp1[0] = f2tf32(bv1.x); bsp1[1] = f2tf32(bv1.y);
        bsp1[2] = f2tf32(bv1.z); bsp1[3] = f2tf32(bv1.w);
    }
    __syncthreads();

    int buf = 0;
    for (int k0 = 0; k0 < K; k0 += 16) {
        const bool has_next = (k0 + 16) < K;
        float4 av0, av1, bv0, bv1;
        if (has_next) {
            const int kn = k0 + 16;
            av0 = *(const float4*)(Ag + (size_t)a_row0 * K + kn + a_c4);
            av1 = *(const float4*)(Ag + (size_t)a_row1 * K + kn + a_c4);
            bv0 = *(const float4*)(Bg + (size_t)(kn + b_row0) * N + b_n4);
            bv1 = *(const float4*)(Bg + (size_t)(kn + b_row1) * N + b_n4);
        }

        const uint32_t* Asb = As[buf];
        const uint32_t* Bsb = Bs[buf];
#pragma unroll
        for (int kk = 0; kk < 16; kk += 8) {
            uint32_t af[4][4];
#pragma unroll
            for (int mt = 0; mt < 4; mt++) {
                const int r0 = wm + mt * 16 + lq;
                af[mt][0] = Asb[r0 * AS_STRIDE + kk + lr];
                af[mt][1] = Asb[(r0 + 8) * AS_STRIDE + kk + lr];
                af[mt][2] = Asb[r0 * AS_STRIDE + kk + lr + 4];
                af[mt][3] = Asb[(r0 + 8) * AS_STRIDE + kk + lr + 4];
            }
            uint32_t bf[4][2];
#pragma unroll
            for (int nt = 0; nt < 4; nt++) {
                const int c0 = wn + nt * 8 + lq;
                bf[nt][0] = Bsb[(kk + lr) * BS_STRIDE + c0];
                bf[nt][1] = Bsb[(kk + lr + 4) * BS_STRIDE + c0];
            }
#pragma unroll
            for (int mt = 0; mt < 4; mt++)
#pragma unroll
                for (int nt = 0; nt < 4; nt++)
                    mma_tf32(acc[mt][nt][0], acc[mt][nt][1],
                             acc[mt][nt][2], acc[mt][nt][3],
                             af[mt][0], af[mt][1], af[mt][2], af[mt][3],
                             bf[nt][0], bf[nt][1]);
        }

        if (has_next) {
            const int nb = buf ^ 1;
            uint32_t* asp0 = &As[nb][a_row0 * AS_STRIDE + a_c4];
            asp0[0] = f2tf32(av0.x); asp0[1] = f2tf32(av0.y);
            asp0[2] = f2tf32(av0.z); asp0[3] = f2tf32(av0.w);
            uint32_t* asp1 = &As[nb][a_row1 * AS_STRIDE + a_c4];
            asp1[0] = f2tf32(av1.x); asp1[1] = f2tf32(av1.y);
            asp1[2] = f2tf32(av1.z); asp1[3] = f2tf32(av1.w);
            uint32_t* bsp0 = &Bs[nb][b_row0 * BS_STRIDE + b_n4];
            bsp0[0] = f2tf32(bv0.x); bsp0[1] = f2tf32(bv0.y);
            bsp0[2] = f2tf32(bv0.z); bsp0[3] = f2tf32(bv0.w);
            uint32_t* bsp1 = &Bs[nb][b_row1 * BS_STRIDE + b_n4];
            bsp1[0] = f2tf32(bv1.x); bsp1[1] = f2tf32(bv1.y);
            bsp1[2] = f2tf32(bv1.z); bsp1[3] = f2tf32(bv1.w);
            __syncthreads();
            buf = nb;
        }
    }

#pragma unroll
    for (int mt = 0; mt < 4; mt++) {
#pragma unroll
        for (int nt = 0; nt < 4; nt++) {
            const int col = bn + wn + nt * 8 + 2 * lr;
#pragma unroll
            for (int half = 0; half < 2; half++) {
                const int row = bm + wm + mt * 16 + lq + half * 8;
                float v0 = acc[mt][nt][half * 2 + 0];
                float v1 = acc[mt][nt][half * 2 + 1];
                if (EPI >= 1) {
                    v0 += bias[col];
                    v1 += bias[col + 1];
                }
                if (EPI == 2) {
                    v0 = gelu_exact(v0);
                    v1 = gelu_exact(v1);
                }
                float2 o = make_float2(v0, v1);
                *(float2*)&C[(size_t)row * N + col] = o;
            }
        }
    }
}

// ---------------- tensor-core flash attention -------------------------------
// Block: 128 q-rows x one (b,h). 8 warps; warp owns 16 q-rows.
// KV tile = 64. All matmuls via mma.sync m16n8k8 tf32.
// Smem: Ks[64][68] (tf32), Vs[64][72] (tf32), Ps[128][68] (Q staging fp32,
// then per-warp-private P tf32). Strides chosen mod-32 = 4 / 8 for
// conflict-free fragment access.
static constexpr int KS_ST = 68;
static constexpr int VS_ST = 72;
static constexpr int PS_ST = 68;
static constexpr int FLASH_SMEM =
    (64 * KS_ST + 64 * VS_ST + 128 * PS_ST) * 4;   // 70656 B

__global__ __launch_bounds__(256) void flash_tc_kernel(
    const float* __restrict__ Qb, const float* __restrict__ Kb,
    const float* __restrict__ Vb, float* __restrict__ Ob)
{
    extern __shared__ uint32_t smu[];
    uint32_t* Ks = smu;
    uint32_t* Vs = smu + 64 * KS_ST;
    uint32_t* Ps = smu + 64 * KS_ST + 64 * VS_ST;
    float*    Psf = (float*)Ps;

    const int tid = threadIdx.x;
    const int warp = tid >> 5;
    const int lane = tid & 31;
    const int lq = lane >> 2;   // 0..7
    const int lr = lane & 3;    // 0..3

    const int b = blockIdx.y / Hh;
    const int h = blockIdx.y % Hh;
    const int q0 = blockIdx.x * 128;
    const int w16 = warp * 16;

    const float scale = 0.125f;   // 64^-0.5

    // ---- stage Q tile [128 x 64] into Psf (coalesced) ----
    {
        const size_t baseQ = ((size_t)(b * Tt + q0)) * Dd + h * HDd;
        for (int it = 0; it < 8; it++) {
            const int id = tid + it * 256;
            const int r = id >> 4, c4 = (id & 15) << 2;
            float4 v = *(const float4*)&Qb[baseQ + (size_t)r * Dd + c4];
            float* p = &Psf[r * PS_ST + c4];
            p[0] = v.x; p[1] = v.y; p[2] = v.z; p[3] = v.w;
        }
    }
    __syncthreads();

    // ---- Q fragments (tf32) held in registers for the whole block ----
    uint32_t qa[8][4];
#pragma unroll
    for (int kk8 = 0; kk8 < 8; kk8++) {
        const int c = kk8 * 8;
        qa[kk8][0] = f2tf32(Psf[(w16 + lq) * PS_ST + c + lr]);
        qa[kk8][1] = f2tf32(Psf[(w16 + lq + 8) * PS_ST + c + lr]);
        qa[kk8][2] = f2tf32(Psf[(w16 + lq) * PS_ST + c + lr + 4]);
        qa[kk8][3] = f2tf32(Psf[(w16 + lq + 8) * PS_ST + c + lr + 4]);
    }
    __syncthreads();   // everyone has Q frags before Ps is reused for P

    float o[8][4];
#pragma unroll
    for (int nt = 0; nt < 8; nt++)
#pragma unroll
        for (int r = 0; r < 4; r++) o[nt][r] = 0.0f;
    float m0 = -INFINITY, m1 = -INFINITY;
    float l0 = 0.0f, l1 = 0.0f;

    for (int kv0 = 0; kv0 < Tt; kv0 += 64) {
        // ---- load K,V tiles (convert to tf32 at store) ----
        const size_t baseKV = ((size_t)(b * Tt + kv0)) * Dd + h * HDd;
#pragma unroll
        for (int it = 0; it < 4; it++) {
            const int id = tid + it * 256;
            const int r = id >> 4, c4 = (id & 15) << 2;
            float4 kv = *(const float4*)&Kb[baseKV + (size_t)r * Dd + c4];
            uint32_t* kp = &Ks[r * KS_ST + c4];
            kp[0] = f2tf32(kv.x); kp[1] = f2tf32(kv.y);
            kp[2] = f2tf32(kv.z); kp[3] = f2tf32(kv.w);
            float4 vv = *(const float4*)&Vb[baseKV + (size_t)r * Dd + c4];
            uint32_t* vp = &Vs[r * VS_ST + c4];
            vp[0] = f2tf32(vv.x); vp[1] = f2tf32(vv.y);
            vp[2] = f2tf32(vv.z); vp[3] = f2tf32(vv.w);
        }
        __syncthreads();

        // ---- S = Q K^T : warp computes 16 x 64 ----
        float s[8][4];
#pragma unroll
        for (int nt = 0; nt < 8; nt++)
#pragma unroll
            for (int r = 0; r < 4; r++) s[nt][r] = 0.0f;

#pragma unroll
        for (int kk8 = 0; kk8 < 8; kk8++) {
            const int c = kk8 * 8;
#pragma unroll
            for (int nt = 0; nt < 8; nt++) {
                const uint32_t b0 = Ks[(nt * 8 + lq) * KS_ST + c + lr];
                const uint32_t b1 = Ks[(nt * 8 + lq) * KS_ST + c + lr + 4];
                mma_tf32(s[nt][0], s[nt][1], s[nt][2], s[nt][3],
                         qa[kk8][0], qa[kk8][1], qa[kk8][2], qa[kk8][3],
                         b0, b1);
            }
        }

        // ---- online softmax on fragments ----
        // rows: r0 = lq, r1 = lq+8 (within warp tile); quad (shfl 1,2) = full row
        float rm0 = -INFINITY, rm1 = -INFINITY;
#pragma unroll
        for (int nt = 0; nt < 8; nt++) {
            rm0 = fmaxf(rm0, fmaxf(s[nt][0], s[nt][1]));
            rm1 = fmaxf(rm1, fmaxf(s[nt][2], s[nt][3]));
        }
        rm0 = fmaxf(rm0, __shfl_xor_sync(0xffffffffu, rm0, 1));
        rm0 = fmaxf(rm0, __shfl_xor_sync(0xffffffffu, rm0, 2));
        rm1 = fmaxf(rm1, __shfl_xor_sync(0xffffffffu, rm1, 1));
        rm1 = fmaxf(rm1, __shfl_xor_sync(0xffffffffu, rm1, 2));
        const float mn0 = fmaxf(m0, rm0 * scale);
        const float mn1 = fmaxf(m1, rm1 * scale);
        const float alpha0 = __expf(m0 - mn0);
        const float alpha1 = __expf(m1 - mn1);

        float rs0 = 0.0f, rs1 = 0.0f;
#pragma unroll
        for (int nt = 0; nt < 8; nt++) {
            float p00 = __expf(s[nt][0] * scale - mn0);
            float p01 = __expf(s[nt][1] * scale - mn0);
            float p10 = __expf(s[nt][2] * scale - mn1);
            float p11 = __expf(s[nt][3] * scale - mn1);
            rs0 += p00 + p01;
            rs1 += p10 + p11;
            const int c = nt * 8 + 2 * lr;
            *(uint2*)&Ps[(w16 + lq) * PS_ST + c] =
                make_uint2(f2tf32(p00), f2tf32(p01));
            *(uint2*)&Ps[(w16 + lq + 8) * PS_ST + c] =
                make_uint2(f2tf32(p10), f2tf32(p11));
        }
        rs0 += __shfl_xor_sync(0xffffffffu, rs0, 1);
        rs0 += __shfl_xor_sync(0xffffffffu, rs0, 2);
        rs1 += __shfl_xor_sync(0xffffffffu, rs1, 1);
        rs1 += __shfl_xor_sync(0xffffffffu, rs1, 2);

        l0 = l0 * alpha0 + rs0;
        l1 = l1 * alpha1 + rs1;
        m0 = mn0;
        m1 = mn1;
#pragma unroll
        for (int nt = 0; nt < 8; nt++) {
            o[nt][0] *= alpha0; o[nt][1] *= alpha0;
            o[nt][2] *= alpha1; o[nt][3] *= alpha1;
        }
        __syncwarp();   // P writes visible to whole warp (warp-private rows)

        // ---- O += P V : warp computes 16 x 64 ----
#pragma unroll
        for (int kk8 = 0; kk8 < 8; kk8++) {
            const int c = kk8 * 8;
            uint32_t pa[4];
            pa[0] = Ps[(w16 + lq) * PS_ST + c + lr];
            pa[1] = Ps[(w16 + lq + 8) * PS_ST + c + lr];
            pa[2] = Ps[(w16 + lq) * PS_ST + c + lr + 4];
            pa[3] = Ps[(w16 + lq + 8) * PS_ST + c + lr + 4];
#pragma unroll
            for (int nt = 0; nt < 8; nt++) {
                const uint32_t b0 = Vs[(c + lr) * VS_ST + nt * 8 + lq];
                const uint32_t b1 = Vs[(c + lr + 4) * VS_ST + nt * 8 + lq];
                mma_tf32(o[nt][0], o[nt][1], o[nt][2], o[nt][3],
                         pa[0], pa[1], pa[2], pa[3], b0, b1);
            }
        }
        __syncthreads();   // PV reads done before next tile's K/V overwrite
    }

    // ---- normalize + write ----
    const float inv0 = 1.0f / l0;
    const float inv1 = 1.0f / l1;
    const int r0 = q0 + w16 + lq;
    const int r1 = r0 + 8;
    const size_t base0 = ((size_t)(b * Tt + r0)) * Dd + h * HDd;
    const size_t base1 = ((size_t)(b * Tt + r1)) * Dd + h * HDd;
#pragma unroll
    for (int nt = 0; nt < 8; nt++) {
        const int c = nt * 8 + 2 * lr;
        *(float2*)&Ob[base0 + c] = make_float2(o[nt][0] * inv0, o[nt][1] * inv0);
        *(float2*)&Ob[base1 + c] = make_float2(o[nt][2] * inv1, o[nt][3] * inv1);
    }
}

// ---------------- residual add + LayerNorm ---------------------------------
__device__ __forceinline__ float block_sum_1024(float v, float* red) {
    const int tid = threadIdx.x;
    __syncthreads();
#pragma unroll
    for (int o = 16; o > 0; o >>= 1)
        v += __shfl_xor_sync(0xffffffffu, v, o);
    if ((tid & 31) == 0) red[tid >> 5] = v;
    __syncthreads();
    float t = (tid < 8) ? red[tid] : 0.0f;
    if (tid < 32) {
#pragma unroll
        for (int o = 4; o > 0; o >>= 1)
            t += __shfl_xor_sync(0xffffffffu, t, o);
        if (tid == 0) red[0] = t;
    }
    __syncthreads();
    return red[0];
}

__global__ __launch_bounds__(256) void add_ln_kernel(
    const float* __restrict__ A, const float* __restrict__ Bv,
    const float* __restrict__ g, const float* __restrict__ be,
    float* __restrict__ out)
{
    __shared__ float red[8];
    const int row = blockIdx.x;
    const int tid = threadIdx.x;
    const size_t base = (size_t)row * Dd;
    const int c = tid * 4;

    float4 a = *(const float4*)&A[base + c];
    float4 b = *(const float4*)&Bv[base + c];
    float v0 = a.x + b.x, v1 = a.y + b.y, v2 = a.z + b.z, v3 = a.w + b.w;

    float s = block_sum_1024(v0 + v1 + v2 + v3, red);
    const float mu = s * (1.0f / Dd);
    float d0 = v0 - mu, d1 = v1 - mu, d2 = v2 - mu, d3 = v3 - mu;
    float q = block_sum_1024(d0 * d0 + d1 * d1 + d2 * d2 + d3 * d3, red);
    const float inv = rsqrtf(q * (1.0f / Dd) + 1e-5f);

    float4 gv = *(const float4*)&g[c];
    float4 bev = *(const float4*)&be[c];
    float4 o;
    o.x = d0 * inv * gv.x + bev.x;
    o.y = d1 * inv * gv.y + bev.y;
    o.z = d2 * inv * gv.z + bev.z;
    o.w = d3 * inv * gv.w + bev.w;
    *(float4*)&out[base + c] = o;
}

// ---------------- orchestration --------------------------------------------
extern "C" void kernel_launch(void* const* d_in, const int* in_sizes, int n_in,
                              void* d_out, int out_size)
{
    const float* x   = (const float*)d_in[0];
    const float* wq  = (const float*)d_in[1];
    const float* wk  = (const float*)d_in[2];
    const float* wv  = (const float*)d_in[3];
    const float* wo  = (const float*)d_in[4];
    const float* w1  = (const float*)d_in[5];
    const float* b1  = (const float*)d_in[6];
    const float* w2  = (const float*)d_in[7];
    const float* b2  = (const float*)d_in[8];
    const float* g1  = (const float*)d_in[9];
    const float* be1 = (const float*)d_in[10];
    const float* g2  = (const float*)d_in[11];
    const float* be2 = (const float*)d_in[12];

    float *Q, *K, *V, *attn, *proj, *h, *ff1, *ff2;
    cudaGetSymbolAddress((void**)&Q,    g_Q);
    cudaGetSymbolAddress((void**)&K,    g_K);
    cudaGetSymbolAddress((void**)&V,    g_V);
    cudaGetSymbolAddress((void**)&attn, g_attn);
    cudaGetSymbolAddress((void**)&proj, g_proj);
    cudaGetSymbolAddress((void**)&h,    g_h);
    cudaGetSymbolAddress((void**)&ff1,  g_ff1);
    cudaGetSymbolAddress((void**)&ff2,  g_ff2);

    cudaFuncSetAttribute(flash_tc_kernel,
                         cudaFuncAttributeMaxDynamicSharedMemorySize, FLASH_SMEM);

    const dim3 blk(256);
    const dim3 gD (Dd  / 128, Mrows / 128);
    const dim3 gDF(DFf / 128, Mrows / 128);

    gemm_tc_kernel<0><<<gD, blk>>>(x, wq, nullptr, Q, Mrows, Dd, Dd);
    gemm_tc_kernel<0><<<gD, blk>>>(x, wk, nullptr, K, Mrows, Dd, Dd);
    gemm_tc_kernel<0><<<gD, blk>>>(x, wv, nullptr, V, Mrows, Dd, Dd);

    flash_tc_kernel<<<dim3(Tt / 128, Bb * Hh), blk, FLASH_SMEM>>>(Q, K, V, attn);

    gemm_tc_kernel<0><<<gD, blk>>>(attn, wo, nullptr, proj, Mrows, Dd, Dd);

    add_ln_kernel<<<Mrows, blk>>>(x, proj, g1, be1, h);

    gemm_tc_kernel<2><<<gDF, blk>>>(h, w1, b1, ff1, Mrows, DFf, Dd);
    gemm_tc_kernel<1><<<gD,  blk>>>(ff1, w2, b2, ff2, Mrows, Dd, DFf);

    add_ln_kernel<<<Mrows, blk>>>(h, ff2, g2, be2, (float*)d_out);
}

// round 5
// speedup vs baseline: 3.1637x; 1.1095x over previous
#include <cuda_runtime.h>
#include <math.h>
#include <stdint.h>

// Problem shape (fixed)
static constexpr int Bb = 4;
static constexpr int Tt = 2048;
static constexpr int Dd = 1024;
static constexpr int Hh = 16;
static constexpr int HDd = 64;
static constexpr int DFf = 4096;
static constexpr int Mrows = Bb * Tt;   // 8192

// ---------------- scratch (device globals; no allocation allowed) ----------
__device__ float g_Q[(size_t)Mrows * Dd];
__device__ float g_K[(size_t)Mrows * Dd];
__device__ float g_V[(size_t)Mrows * Dd];
__device__ float g_attn[(size_t)Mrows * Dd];
__device__ float g_proj[(size_t)Mrows * Dd];
__device__ float g_h[(size_t)Mrows * Dd];
__device__ float g_ff1[(size_t)Mrows * DFf];
__device__ float g_ff2[(size_t)Mrows * Dd];

// ---------------- helpers ----------------
__device__ __forceinline__ float gelu_exact(float x) {
    return 0.5f * x * (1.0f + erff(x * 0.70710678118654752f));
}

// mma consumes raw fp32 bits as tf32 (HW truncates low mantissa bits).
__device__ __forceinline__ void mma_tf32(
    float& c0, float& c1, float& c2, float& c3,
    uint32_t a0, uint32_t a1, uint32_t a2, uint32_t a3,
    uint32_t b0, uint32_t b1)
{
    asm volatile(
        "mma.sync.aligned.m16n8k8.row.col.f32.tf32.tf32.f32 "
        "{%0,%1,%2,%3}, {%4,%5,%6,%7}, {%8,%9}, {%0,%1,%2,%3};\n"
        : "+f"(c0), "+f"(c1), "+f"(c2), "+f"(c3)
        : "r"(a0), "r"(a1), "r"(a2), "r"(a3), "r"(b0), "r"(b1));
}

__device__ __forceinline__ void cp_async16(uint32_t smem_addr, const void* gptr) {
    asm volatile("cp.async.cg.shared.global [%0], [%1], 16;\n"
                 :: "r"(smem_addr), "l"(gptr));
}
__device__ __forceinline__ void cp_commit() {
    asm volatile("cp.async.commit_group;\n");
}
template <int N>
__device__ __forceinline__ void cp_wait() {
    asm volatile("cp.async.wait_group %0;\n" :: "n"(N));
}

// ---------------- tf32 tensor-core GEMM, cp.async 4-stage -------------------
// C[M,N] = A[M,K] @ B[K,N] (+bias)(+gelu)
// Block 128x128, BK=16, 256 threads (8 warps), warp tile 64x32.
static constexpr int AS_STRIDE = 20;    // 16 k + 4 pad (words)
static constexpr int BS_STRIDE = 136;   // 128 n + 8 pad
static constexpr int ASZ = 128 * AS_STRIDE;          // words per A stage
static constexpr int BSZ = 16 * BS_STRIDE;           // words per B stage
static constexpr int STAGE_W = ASZ + BSZ;
static constexpr int GSTAGES = 4;
static constexpr int GEMM_SMEM = GSTAGES * STAGE_W * 4;   // 75776 B

template <int EPI>
__global__ __launch_bounds__(256) void gemm_cp_kernel(
    const float* __restrict__ A, const float* __restrict__ Bm,
    const float* __restrict__ bias, float* __restrict__ C,
    int M, int N, int K)
{
    extern __shared__ uint32_t sh[];
    const uint32_t sbase = (uint32_t)__cvta_generic_to_shared(sh);

    const int tid = threadIdx.x;
    const int warp = tid >> 5;
    const int lane = tid & 31;
    const int lq = lane >> 2;
    const int lr = lane & 3;

    const int bm = blockIdx.y * 128;
    const int bn = blockIdx.x * 128;
    const int wm = (warp & 1) * 64;
    const int wn = (warp >> 1) * 32;

    const int a_row0 = tid >> 2;
    const int a_row1 = (tid + 256) >> 2;
    const int a_c4   = (tid & 3) * 4;
    const int b_row0 = tid >> 5;
    const int b_row1 = (tid + 256) >> 5;
    const int b_n4   = (tid & 31) * 4;

    const float* Ag = A + (size_t)bm * K;
    const float* Bg = Bm + bn;

    // per-thread fixed smem targets (byte addresses), stage-relative
    const uint32_t sa0 = (a_row0 * AS_STRIDE + a_c4) * 4;
    const uint32_t sa1 = (a_row1 * AS_STRIDE + a_c4) * 4;
    const uint32_t sb0 = (ASZ + b_row0 * BS_STRIDE + b_n4) * 4;
    const uint32_t sb1 = (ASZ + b_row1 * BS_STRIDE + b_n4) * 4;

    const int KT = K / 16;

    auto issue = [&](int kt, int stage) {
        const uint32_t st = sbase + (uint32_t)(stage * STAGE_W * 4);
        const int k0 = kt * 16;
        cp_async16(st + sa0, Ag + (size_t)a_row0 * K + k0 + a_c4);
        cp_async16(st + sa1, Ag + (size_t)a_row1 * K + k0 + a_c4);
        cp_async16(st + sb0, Bg + (size_t)(k0 + b_row0) * N + b_n4);
        cp_async16(st + sb1, Bg + (size_t)(k0 + b_row1) * N + b_n4);
    };

    // prologue: 3 tiles in flight
#pragma unroll
    for (int s = 0; s < GSTAGES - 1; s++) {
        issue(s, s);
        cp_commit();
    }

    float acc[4][4][4];
#pragma unroll
    for (int i = 0; i < 4; i++)
#pragma unroll
        for (int j = 0; j < 4; j++)
#pragma unroll
            for (int r = 0; r < 4; r++) acc[i][j][r] = 0.0f;

    for (int it = 0; it < KT; ++it) {
        cp_wait<GSTAGES - 2>();   // tile `it` resident
        __syncthreads();          // publish to all threads; stage (it-1)%4 free
        if (it + GSTAGES - 1 < KT) issue(it + GSTAGES - 1, (it + GSTAGES - 1) & 3);
        cp_commit();

        const uint32_t* Asb = sh + (it & 3) * STAGE_W;
        const uint32_t* Bsb = Asb + ASZ;
#pragma unroll
        for (int kk = 0; kk < 16; kk += 8) {
            uint32_t af[4][4];
#pragma unroll
            for (int mt = 0; mt < 4; mt++) {
                const int r0 = wm + mt * 16 + lq;
                af[mt][0] = Asb[r0 * AS_STRIDE + kk + lr];
                af[mt][1] = Asb[(r0 + 8) * AS_STRIDE + kk + lr];
                af[mt][2] = Asb[r0 * AS_STRIDE + kk + lr + 4];
                af[mt][3] = Asb[(r0 + 8) * AS_STRIDE + kk + lr + 4];
            }
            uint32_t bf[4][2];
#pragma unroll
            for (int nt = 0; nt < 4; nt++) {
                const int c0 = wn + nt * 8 + lq;
                bf[nt][0] = Bsb[(kk + lr) * BS_STRIDE + c0];
                bf[nt][1] = Bsb[(kk + lr + 4) * BS_STRIDE + c0];
            }
#pragma unroll
            for (int mt = 0; mt < 4; mt++)
#pragma unroll
                for (int nt = 0; nt < 4; nt++)
                    mma_tf32(acc[mt][nt][0], acc[mt][nt][1],
                             acc[mt][nt][2], acc[mt][nt][3],
                             af[mt][0], af[mt][1], af[mt][2], af[mt][3],
                             bf[nt][0], bf[nt][1]);
        }
    }

    // ---- epilogue ----
#pragma unroll
    for (int mt = 0; mt < 4; mt++) {
#pragma unroll
        for (int nt = 0; nt < 4; nt++) {
            const int col = bn + wn + nt * 8 + 2 * lr;
#pragma unroll
            for (int half = 0; half < 2; half++) {
                const int row = bm + wm + mt * 16 + lq + half * 8;
                float v0 = acc[mt][nt][half * 2 + 0];
                float v1 = acc[mt][nt][half * 2 + 1];
                if (EPI >= 1) {
                    v0 += bias[col];
                    v1 += bias[col + 1];
                }
                if (EPI == 2) {
                    v0 = gelu_exact(v0);
                    v1 = gelu_exact(v1);
                }
                *(float2*)&C[(size_t)row * N + col] = make_float2(v0, v1);
            }
        }
    }
}

// ---------------- tensor-core flash attention, cp.async double-buffer -------
// Block: 128 q-rows x one (b,h). 8 warps; warp owns 16 q-rows. KV tile = 64.
static constexpr int KS_ST = 68;
static constexpr int VS_ST = 72;
static constexpr int PS_ST = 68;
static constexpr int KBUF = 64 * KS_ST;    // words
static constexpr int VBUF = 64 * VS_ST;
static constexpr int FLASH_SMEM = (2 * KBUF + 2 * VBUF + 128 * PS_ST) * 4; // 106496 B

__global__ __launch_bounds__(256) void flash_tc_kernel(
    const float* __restrict__ Qb, const float* __restrict__ Kb,
    const float* __restrict__ Vb, float* __restrict__ Ob)
{
    extern __shared__ uint32_t smu[];
    uint32_t* Ks[2] = { smu, smu + KBUF };
    uint32_t* Vs[2] = { smu + 2 * KBUF, smu + 2 * KBUF + VBUF };
    uint32_t* Ps = smu + 2 * KBUF + 2 * VBUF;
    float*    Psf = (float*)Ps;
    const uint32_t sbase = (uint32_t)__cvta_generic_to_shared(smu);

    const int tid = threadIdx.x;
    const int warp = tid >> 5;
    const int lane = tid & 31;
    const int lq = lane >> 2;   // 0..7
    const int lr = lane & 3;    // 0..3

    const int b = blockIdx.y / Hh;
    const int h = blockIdx.y % Hh;
    const int q0 = blockIdx.x * 128;
    const int w16 = warp * 16;

    const float scale = 0.125f;   // 64^-0.5

    // per-thread KV load geometry: 4 (row, col4) pairs covering 64x64
    int kv_r[4], kv_c4[4];
#pragma unroll
    for (int it = 0; it < 4; it++) {
        const int id = tid + it * 256;
        kv_r[it] = id >> 4;
        kv_c4[it] = (id & 15) << 2;
    }

    auto issue_kv = [&](int kv_tile, int buf) {
        const size_t baseKV = ((size_t)(b * Tt + kv_tile * 64)) * Dd + h * HDd;
        const uint32_t kst = sbase + (uint32_t)(buf * KBUF * 4);
        const uint32_t vst = sbase + (uint32_t)((2 * KBUF + buf * VBUF) * 4);
#pragma unroll
        for (int it = 0; it < 4; it++) {
            const size_t g = baseKV + (size_t)kv_r[it] * Dd + kv_c4[it];
            cp_async16(kst + (kv_r[it] * KS_ST + kv_c4[it]) * 4, Kb + g);
            cp_async16(vst + (kv_r[it] * VS_ST + kv_c4[it]) * 4, Vb + g);
        }
    };

    // prefetch KV tile 0 while staging Q
    issue_kv(0, 0);
    cp_commit();

    // ---- stage Q tile [128 x 64] into Psf (coalesced) ----
    {
        const size_t baseQ = ((size_t)(b * Tt + q0)) * Dd + h * HDd;
#pragma unroll
        for (int it = 0; it < 8; it++) {
            const int id = tid + it * 256;
            const int r = id >> 4, c4 = (id & 15) << 2;
            float4 v = *(const float4*)&Qb[baseQ + (size_t)r * Dd + c4];
            float* p = &Psf[r * PS_ST + c4];
            p[0] = v.x; p[1] = v.y; p[2] = v.z; p[3] = v.w;
        }
    }
    __syncthreads();

    // ---- Q fragments (raw fp32 bits) held in registers ----
    uint32_t qa[8][4];
#pragma unroll
    for (int kk8 = 0; kk8 < 8; kk8++) {
        const int c = kk8 * 8;
        qa[kk8][0] = Ps[(w16 + lq) * PS_ST + c + lr];
        qa[kk8][1] = Ps[(w16 + lq + 8) * PS_ST + c + lr];
        qa[kk8][2] = Ps[(w16 + lq) * PS_ST + c + lr + 4];
        qa[kk8][3] = Ps[(w16 + lq + 8) * PS_ST + c + lr + 4];
    }
    __syncthreads();   // Q frags read before Ps reused for P

    float o[8][4];
#pragma unroll
    for (int nt = 0; nt < 8; nt++)
#pragma unroll
        for (int r = 0; r < 4; r++) o[nt][r] = 0.0f;
    float m0 = -INFINITY, m1 = -INFINITY;
    float l0 = 0.0f, l1 = 0.0f;

    const int NT = Tt / 64;   // 32
    for (int t = 0; t < NT; ++t) {
        // prefetch next tile (safe: trailing sync of t-1 has passed)
        if (t + 1 < NT) issue_kv(t + 1, (t + 1) & 1);
        cp_commit();
        cp_wait<1>();      // tile t resident (next may be in flight)
        __syncthreads();   // publish tile t to all threads

        const uint32_t* Kst = Ks[t & 1];
        const uint32_t* Vst = Vs[t & 1];

        // ---- S = Q K^T : warp computes 16 x 64 ----
        float s[8][4];
#pragma unroll
        for (int nt = 0; nt < 8; nt++)
#pragma unroll
            for (int r = 0; r < 4; r++) s[nt][r] = 0.0f;

#pragma unroll
        for (int kk8 = 0; kk8 < 8; kk8++) {
            const int c = kk8 * 8;
#pragma unroll
            for (int nt = 0; nt < 8; nt++) {
                const uint32_t b0 = Kst[(nt * 8 + lq) * KS_ST + c + lr];
                const uint32_t b1 = Kst[(nt * 8 + lq) * KS_ST + c + lr + 4];
                mma_tf32(s[nt][0], s[nt][1], s[nt][2], s[nt][3],
                         qa[kk8][0], qa[kk8][1], qa[kk8][2], qa[kk8][3],
                         b0, b1);
            }
        }

        // ---- online softmax on fragments ----
        float rm0 = -INFINITY, rm1 = -INFINITY;
#pragma unroll
        for (int nt = 0; nt < 8; nt++) {
            rm0 = fmaxf(rm0, fmaxf(s[nt][0], s[nt][1]));
            rm1 = fmaxf(rm1, fmaxf(s[nt][2], s[nt][3]));
        }
        rm0 = fmaxf(rm0, __shfl_xor_sync(0xffffffffu, rm0, 1));
        rm0 = fmaxf(rm0, __shfl_xor_sync(0xffffffffu, rm0, 2));
        rm1 = fmaxf(rm1, __shfl_xor_sync(0xffffffffu, rm1, 1));
        rm1 = fmaxf(rm1, __shfl_xor_sync(0xffffffffu, rm1, 2));
        const float mn0 = fmaxf(m0, rm0 * scale);
        const float mn1 = fmaxf(m1, rm1 * scale);
        const float alpha0 = __expf(m0 - mn0);
        const float alpha1 = __expf(m1 - mn1);

        float rs0 = 0.0f, rs1 = 0.0f;
#pragma unroll
        for (int nt = 0; nt < 8; nt++) {
            float p00 = __expf(s[nt][0] * scale - mn0);
            float p01 = __expf(s[nt][1] * scale - mn0);
            float p10 = __expf(s[nt][2] * scale - mn1);
            float p11 = __expf(s[nt][3] * scale - mn1);
            rs0 += p00 + p01;
            rs1 += p10 + p11;
            const int c = nt * 8 + 2 * lr;
            *(uint2*)&Ps[(w16 + lq) * PS_ST + c] =
                make_uint2(__float_as_uint(p00), __float_as_uint(p01));
            *(uint2*)&Ps[(w16 + lq + 8) * PS_ST + c] =
                make_uint2(__float_as_uint(p10), __float_as_uint(p11));
        }
        rs0 += __shfl_xor_sync(0xffffffffu, rs0, 1);
        rs0 += __shfl_xor_sync(0xffffffffu, rs0, 2);
        rs1 += __shfl_xor_sync(0xffffffffu, rs1, 1);
        rs1 += __shfl_xor_sync(0xffffffffu, rs1, 2);

        l0 = l0 * alpha0 + rs0;
        l1 = l1 * alpha1 + rs1;
        m0 = mn0;
        m1 = mn1;
#pragma unroll
        for (int nt = 0; nt < 8; nt++) {
            o[nt][0] *= alpha0; o[nt][1] *= alpha0;
            o[nt][2] *= alpha1; o[nt][3] *= alpha1;
        }
        __syncwarp();   // P rows are warp-private

        // ---- O += P V : warp computes 16 x 64 ----
#pragma unroll
        for (int kk8 = 0; kk8 < 8; kk8++) {
            const int c = kk8 * 8;
            uint32_t pa[4];
            pa[0] = Ps[(w16 + lq) * PS_ST + c + lr];
            pa[1] = Ps[(w16 + lq + 8) * PS_ST + c + lr];
            pa[2] = Ps[(w16 + lq) * PS_ST + c + lr + 4];
            pa[3] = Ps[(w16 + lq + 8) * PS_ST + c + lr + 4];
#pragma unroll
            for (int nt = 0; nt < 8; nt++) {
                const uint32_t b0 = Vst[(c + lr) * VS_ST + nt * 8 + lq];
                const uint32_t b1 = Vst[(c + lr + 4) * VS_ST + nt * 8 + lq];
                mma_tf32(o[nt][0], o[nt][1], o[nt][2], o[nt][3],
                         pa[0], pa[1], pa[2], pa[3], b0, b1);
            }
        }
        __syncthreads();   // all reads of this KV buffer done before its reuse
    }

    // ---- normalize + write ----
    const float inv0 = 1.0f / l0;
    const float inv1 = 1.0f / l1;
    const int r0 = q0 + w16 + lq;
    const int r1 = r0 + 8;
    const size_t base0 = ((size_t)(b * Tt + r0)) * Dd + h * HDd;
    const size_t base1 = ((size_t)(b * Tt + r1)) * Dd + h * HDd;
#pragma unroll
    for (int nt = 0; nt < 8; nt++) {
        const int c = nt * 8 + 2 * lr;
        *(float2*)&Ob[base0 + c] = make_float2(o[nt][0] * inv0, o[nt][1] * inv0);
        *(float2*)&Ob[base1 + c] = make_float2(o[nt][2] * inv1, o[nt][3] * inv1);
    }
}

// ---------------- residual add + LayerNorm ---------------------------------
__device__ __forceinline__ float block_sum_1024(float v, float* red) {
    const int tid = threadIdx.x;
    __syncthreads();
#pragma unroll
    for (int o = 16; o > 0; o >>= 1)
        v += __shfl_xor_sync(0xffffffffu, v, o);
    if ((tid & 31) == 0) red[tid >> 5] = v;
    __syncthreads();
    float t = (tid < 8) ? red[tid] : 0.0f;
    if (tid < 32) {
#pragma unroll
        for (int o = 4; o > 0; o >>= 1)
            t += __shfl_xor_sync(0xffffffffu, t, o);
        if (tid == 0) red[0] = t;
    }
    __syncthreads();
    return red[0];
}

__global__ __launch_bounds__(256) void add_ln_kernel(
    const float* __restrict__ A, const float* __restrict__ Bv,
    const float* __restrict__ g, const float* __restrict__ be,
    float* __restrict__ out)
{
    __shared__ float red[8];
    const int row = blockIdx.x;
    const int tid = threadIdx.x;
    const size_t base = (size_t)row * Dd;
    const int c = tid * 4;

    float4 a = *(const float4*)&A[base + c];
    float4 b = *(const float4*)&Bv[base + c];
    float v0 = a.x + b.x, v1 = a.y + b.y, v2 = a.z + b.z, v3 = a.w + b.w;

    float s = block_sum_1024(v0 + v1 + v2 + v3, red);
    const float mu = s * (1.0f / Dd);
    float d0 = v0 - mu, d1 = v1 - mu, d2 = v2 - mu, d3 = v3 - mu;
    float q = block_sum_1024(d0 * d0 + d1 * d1 + d2 * d2 + d3 * d3, red);
    const float inv = rsqrtf(q * (1.0f / Dd) + 1e-5f);

    float4 gv = *(const float4*)&g[c];
    float4 bev = *(const float4*)&be[c];
    float4 o;
    o.x = d0 * inv * gv.x + bev.x;
    o.y = d1 * inv * gv.y + bev.y;
    o.z = d2 * inv * gv.z + bev.z;
    o.w = d3 * inv * gv.w + bev.w;
    *(float4*)&out[base + c] = o;
}

// ---------------- orchestration --------------------------------------------
extern "C" void kernel_launch(void* const* d_in, const int* in_sizes, int n_in,
                              void* d_out, int out_size)
{
    const float* x   = (const float*)d_in[0];
    const float* wq  = (const float*)d_in[1];
    const float* wk  = (const float*)d_in[2];
    const float* wv  = (const float*)d_in[3];
    const float* wo  = (const float*)d_in[4];
    const float* w1  = (const float*)d_in[5];
    const float* b1  = (const float*)d_in[6];
    const float* w2  = (const float*)d_in[7];
    const float* b2  = (const float*)d_in[8];
    const float* g1  = (const float*)d_in[9];
    const float* be1 = (const float*)d_in[10];
    const float* g2  = (const float*)d_in[11];
    const float* be2 = (const float*)d_in[12];

    float *Q, *K, *V, *attn, *proj, *h, *ff1, *ff2;
    cudaGetSymbolAddress((void**)&Q,    g_Q);
    cudaGetSymbolAddress((void**)&K,    g_K);
    cudaGetSymbolAddress((void**)&V,    g_V);
    cudaGetSymbolAddress((void**)&attn, g_attn);
    cudaGetSymbolAddress((void**)&proj, g_proj);
    cudaGetSymbolAddress((void**)&h,    g_h);
    cudaGetSymbolAddress((void**)&ff1,  g_ff1);
    cudaGetSymbolAddress((void**)&ff2,  g_ff2);

    cudaFuncSetAttribute(gemm_cp_kernel<0>,
                         cudaFuncAttributeMaxDynamicSharedMemorySize, GEMM_SMEM);
    cudaFuncSetAttribute(gemm_cp_kernel<1>,
                         cudaFuncAttributeMaxDynamicSharedMemorySize, GEMM_SMEM);
    cudaFuncSetAttribute(gemm_cp_kernel<2>,
                         cudaFuncAttributeMaxDynamicSharedMemorySize, GEMM_SMEM);
    cudaFuncSetAttribute(flash_tc_kernel,
                         cudaFuncAttributeMaxDynamicSharedMemorySize, FLASH_SMEM);

    const dim3 blk(256);
    const dim3 gD (Dd  / 128, Mrows / 128);
    const dim3 gDF(DFf / 128, Mrows / 128);

    gemm_cp_kernel<0><<<gD, blk, GEMM_SMEM>>>(x, wq, nullptr, Q, Mrows, Dd, Dd);
    gemm_cp_kernel<0><<<gD, blk, GEMM_SMEM>>>(x, wk, nullptr, K, Mrows, Dd, Dd);
    gemm_cp_kernel<0><<<gD, blk, GEMM_SMEM>>>(x, wv, nullptr, V, Mrows, Dd, Dd);

    flash_tc_kernel<<<dim3(Tt / 128, Bb * Hh), blk, FLASH_SMEM>>>(Q, K, V, attn);

    gemm_cp_kernel<0><<<gD, blk, GEMM_SMEM>>>(attn, wo, nullptr, proj, Mrows, Dd, Dd);

    add_ln_kernel<<<Mrows, blk>>>(x, proj, g1, be1, h);

    gemm_cp_kernel<2><<<gDF, blk, GEMM_SMEM>>>(h, w1, b1, ff1, Mrows, DFf, Dd);
    gemm_cp_kernel<1><<<gD,  blk, GEMM_SMEM>>>(ff1, w2, b2, ff2, Mrows, Dd, DFf);

    add_ln_kernel<<<Mrows, blk>>>(h, ff2, g2, be2, (float*)d_out);
}